// round 2
// baseline (speedup 1.0000x reference)
#include <cuda_runtime.h>
#include <cstdint>

typedef unsigned int u32;
typedef unsigned long long u64;

#define NT 512
#define SLEN 65544
#define NEMB 65536

// ---------------- scratch (device globals; no allocation) ----------------
__device__ u32 g_stream[(NT * SLEN) / 4 + 32];   // packed stream bytes (+pad)
__device__ u32 g_man[(NEMB * 256) / 4];          // packed mantissa bytes
__device__ u32 g_exp[(NEMB * 256) / 4];          // decoded exponent bytes
__device__ uint2 g_lut[4096];                    // {freq, bias = slot - cum}
__device__ u32 g_symtab[4096];

// ---------------- build fused per-slot LUT ----------------
__global__ void k_build_lut(const int* __restrict__ tables,
                            const int* __restrict__ slot_map) {
    int s = blockIdx.x * blockDim.x + threadIdx.x;
    if (s < 4096) {
        u32 sym = (u32)slot_map[s];
        u32 t = (u32)tables[sym];
        u32 freq = t >> 16;
        u32 cum = t & 0xFFFFu;
        g_lut[s] = make_uint2(freq, (u32)s - cum);
        g_symtab[s] = sym;
    }
}

// ---------------- pack int32-per-byte arrays into real bytes ----------------
__global__ void k_pack_stream(const int4* __restrict__ in, int n4) {
    int i = blockIdx.x * blockDim.x + threadIdx.x;
    if (i < n4) {
        int4 v = in[i];
        g_stream[i] = (u32)(v.x & 0xFF) | ((u32)(v.y & 0xFF) << 8) |
                      ((u32)(v.z & 0xFF) << 16) | ((u32)(v.w & 0xFF) << 24);
    }
}

__global__ void k_pack_man(const int4* __restrict__ in, int n4) {
    int i = blockIdx.x * blockDim.x + threadIdx.x;
    if (i < n4) {
        int4 v = in[i];
        g_man[i] = (u32)(v.x & 0xFF) | ((u32)(v.y & 0xFF) << 8) |
                   ((u32)(v.z & 0xFF) << 16) | ((u32)(v.w & 0xFF) << 24);
    }
}

// byte-swap an 8-byte little-endian load so the FIRST stream byte sits at the MSB
__device__ __forceinline__ u64 bswap_pair(uint2 v) {
    u32 hiw = __byte_perm(v.x, 0, 0x0123);
    u32 low = __byte_perm(v.y, 0, 0x0123);
    return ((u64)hiw << 32) | (u64)low;
}

// ---------------- the serial rANS decode: 512 chains, 1 thread each ----------------
__global__ void __launch_bounds__(32, 1)
k_decode(const int* __restrict__ tile_offsets, const int* __restrict__ states) {
    __shared__ uint2 LUT[4096];
    __shared__ unsigned char SYMT[4096];
    int tid = threadIdx.x;
#pragma unroll 4
    for (int i = tid; i < 4096; i += 32) {
        LUT[i] = g_lut[i];
        SYMT[i] = (unsigned char)g_symtab[i];
    }
    __syncthreads();

    int tile = blockIdx.x * 32 + tid;
    u32 state = (u32)states[tile];
    const uint2* sp = (const uint2*)(g_stream + (tile_offsets[tile] >> 2));

    // 16-byte register reservoir (left-aligned, MSB = next stream byte)
    // + 2-deep prefetch stage
    u64 hi = bswap_pair(__ldg(sp + 0));
    u64 lo = bswap_pair(__ldg(sp + 1));
    u64 n0 = bswap_pair(__ldg(sp + 2));
    u64 n1 = bswap_pair(__ldg(sp + 3));
    int ptr = 4;     // u64 units
    int avail = 16;  // valid bytes in (hi:lo)

    // output word index: row = (tile>>3)*1024 + (blk>>3), colword = (tile&7)*8 + (blk&7)
    u32 outw = (u32)((tile >> 3) * 1024) * 64u + (u32)(tile & 7) * 8u;

    for (int blk = 0; blk < 8192; ++blk) {
        uint2 fresh = __ldg(sp + ptr);  // early prefetch; merged (or discarded) at block end
        u32 acc = 0;
#pragma unroll
        for (int s = 0; s < 4; ++s) {
            u32 slot = state & 4095u;
            uint2 e = LUT[slot];                 // LDS.64 on the critical chain
            u32 sym = (u32)SYMT[slot];           // off critical path
            state = e.x * (state >> 12) + e.y;   // freq*(state>>12) + bias
            u32 b0 = (u32)(hi >> 56);
            u32 b01 = (u32)(hi >> 48);
            bool p1 = state < (1u << 23);        // need >=1 renorm byte
            bool p2 = state < (1u << 15);        // need exactly 2 (implies p1)
            u32 c1 = (state << 8) | b0;
            u32 c2 = (state << 16) | b01;
            u32 ns = p1 ? c1 : state;
            ns = p2 ? c2 : ns;
            // consume 0/1/2 bytes from reservoir (off critical path)
            u64 h1 = (hi << 8) | (lo >> 56);
            u64 l1 = lo << 8;
            hi = p1 ? h1 : hi;
            lo = p1 ? l1 : lo;
            u64 h2 = (hi << 8) | (lo >> 56);
            u64 l2 = lo << 8;
            hi = p2 ? h2 : hi;
            lo = p2 ? l2 : lo;
            avail -= (int)p1 + (int)p2;
            state = ns;
            acc |= sym << (8 * s);
        }
        g_exp[outw] = acc;
        outw += ((blk & 7) == 7) ? 57u : 1u;

        // branchless refill: append n0's 8 bytes at byte position `avail` when avail<8
        bool need = avail < 8;
        unsigned a = need ? (unsigned)avail : 8u;
        unsigned a4 = a * 4u;          // <= 32, double-shift avoids shift-by-64 UB
        unsigned s4 = (8u - a) * 4u;   // <= 32
        u64 add_hi = (n0 >> a4) >> a4;
        u64 add_lo = (n0 << s4) << s4;
        hi = need ? (hi | add_hi) : hi;
        lo = need ? (lo | add_lo) : lo;
        n0 = need ? n1 : n0;
        n1 = need ? bswap_pair(fresh) : n1;
        ptr += need ? 1 : 0;
        avail += need ? 8 : 0;
    }
}

// ---------------- gather: out[l, :] = f32(bf16(exp<<8 | man)) of row x[l] ----------------
__global__ void __launch_bounds__(256)
k_gather(const int* __restrict__ x, float4* __restrict__ out) {
    int l = blockIdx.x * 4 + (threadIdx.x >> 6);
    int c = threadIdx.x & 63;
    int row = x[l];
    u32 e = g_exp[row * 64 + c];
    u32 m = g_man[row * 64 + c];
    float4 o;
    o.x = __uint_as_float(((e & 0xFFu) << 24) | ((m & 0xFFu) << 16));
    o.y = __uint_as_float((((e >> 8) & 0xFFu) << 24) | (((m >> 8) & 0xFFu) << 16));
    o.z = __uint_as_float((((e >> 16) & 0xFFu) << 24) | (((m >> 16) & 0xFFu) << 16));
    o.w = __uint_as_float((e & 0xFF000000u) | ((m >> 24) << 16));
    out[(size_t)l * 64 + (size_t)c] = o;
}

// ---------------- launch ----------------
extern "C" void kernel_launch(void* const* d_in, const int* in_sizes, int n_in,
                              void* d_out, int out_size) {
    const int* x       = (const int*)d_in[0];
    const int* stream  = (const int*)d_in[1];
    const int* states  = (const int*)d_in[2];
    const int* tables  = (const int*)d_in[3];
    const int* slotmap = (const int*)d_in[4];
    const int* toffs   = (const int*)d_in[5];
    // d_in[6] = tile_max_lens (uniform; unused)
    const int* manraw  = (const int*)d_in[7];
    float* out = (float*)d_out;

    k_build_lut<<<16, 256>>>(tables, slotmap);

    int n4s = (NT * SLEN) / 4;          // 8,389,632
    k_pack_stream<<<(n4s + 255) / 256, 256>>>((const int4*)stream, n4s);

    int n4m = (NEMB * 256) / 4;         // 4,194,304
    k_pack_man<<<(n4m + 255) / 256, 256>>>((const int4*)manraw, n4m);

    k_decode<<<16, 32>>>(toffs, states);

    k_gather<<<65536, 256>>>(x, (float4*)out);
}

// round 3
// speedup vs baseline: 1.5196x; 1.5196x over previous
#include <cuda_runtime.h>
#include <cstdint>

typedef unsigned int u32;
typedef unsigned long long u64;

#define NT 512
#define SLEN 65544
#define NEMB 65536

// ---------------- scratch (device globals; no allocation) ----------------
__device__ u32 g_stream[(NT * SLEN) / 4 + 64];   // packed stream bytes (+pad)
__device__ u32 g_man[(NEMB * 256) / 4];          // packed mantissa bytes
__device__ u32 g_exp[(NEMB * 256) / 4];          // decoded exponent bytes
__device__ uint2 g_lut[4096];                    // {freq, bias = slot - cum}
__device__ u32 g_symtab[4096];

// ---------------- build fused per-slot LUT ----------------
__global__ void k_build_lut(const int* __restrict__ tables,
                            const int* __restrict__ slot_map) {
    int s = blockIdx.x * blockDim.x + threadIdx.x;
    if (s < 4096) {
        u32 sym = (u32)slot_map[s];
        u32 t = (u32)tables[sym];
        u32 freq = t >> 16;
        u32 cum = t & 0xFFFFu;
        g_lut[s] = make_uint2(freq, (u32)s - cum);
        g_symtab[s] = sym;
    }
}

// ---------------- pack int32-per-byte arrays into real bytes ----------------
__global__ void k_pack_stream(const int4* __restrict__ in, int n4) {
    int i = blockIdx.x * blockDim.x + threadIdx.x;
    if (i < n4) {
        int4 v = in[i];
        g_stream[i] = (u32)(v.x & 0xFF) | ((u32)(v.y & 0xFF) << 8) |
                      ((u32)(v.z & 0xFF) << 16) | ((u32)(v.w & 0xFF) << 24);
    }
}

__global__ void k_pack_man(const int4* __restrict__ in, int n4) {
    int i = blockIdx.x * blockDim.x + threadIdx.x;
    if (i < n4) {
        int4 v = in[i];
        g_man[i] = (u32)(v.x & 0xFF) | ((u32)(v.y & 0xFF) << 8) |
                   ((u32)(v.z & 0xFF) << 16) | ((u32)(v.w & 0xFF) << 24);
    }
}

// byte-swap an 8-byte little-endian load so the FIRST stream byte sits at the MSB
__device__ __forceinline__ u64 bswap_pair(uint2 v) {
    u32 hiw = __byte_perm(v.x, 0, 0x0123);
    u32 low = __byte_perm(v.y, 0, 0x0123);
    return ((u64)hiw << 32) | (u64)low;
}

// ---------------- the serial rANS decode ----------------
// One tile per block; lanes cooperatively stage the LUT in smem, lane 0 runs
// the serial chain alone (zero LDS bank conflicts, own SMSP issue slot).
__global__ void __launch_bounds__(32, 1)
k_decode(const int* __restrict__ tile_offsets, const int* __restrict__ states) {
    __shared__ uint2 LUT[4096];
    __shared__ unsigned char SYMT[4096];
    int tid = threadIdx.x;
#pragma unroll 4
    for (int i = tid; i < 4096; i += 32) {
        LUT[i] = g_lut[i];
        SYMT[i] = (unsigned char)g_symtab[i];
    }
    __syncthreads();
    if (tid != 0) return;

    int tile = blockIdx.x;
    u32 state = (u32)states[tile];
    const uint2* sp = (const uint2*)(g_stream + (tile_offsets[tile] >> 2));

    // 16-byte register reservoir (left-aligned, MSB = next stream byte)
    // + 3-deep prefetch stage so refill never waits on L2/DRAM
    u64 hi = bswap_pair(__ldg(sp + 0));
    u64 lo = bswap_pair(__ldg(sp + 1));
    u64 n0 = bswap_pair(__ldg(sp + 2));
    u64 n1 = bswap_pair(__ldg(sp + 3));
    u64 n2 = bswap_pair(__ldg(sp + 4));
    int ptr = 5;     // u64 units
    int avail = 16;  // valid bytes in (hi:lo)

    // output word index: row = (tile>>3)*1024 + (blk>>3), colword = (tile&7)*8 + (blk&7)
    u32 outw = (u32)((tile >> 3) * 1024) * 64u + (u32)(tile & 7) * 8u;

    for (int blk = 0; blk < 8192; ++blk) {
        uint2 fresh = __ldg(sp + ptr);  // early prefetch; merged (or discarded) at block end
        u32 acc = 0;
#pragma unroll
        for (int s = 0; s < 4; ++s) {
            u32 slot = state & 4095u;
            uint2 e = LUT[slot];                 // LDS.64 on the critical chain
            u32 sym = (u32)SYMT[slot];           // off critical path
            state = e.x * (state >> 12) + e.y;   // freq*(state>>12) + bias
            u32 b0 = (u32)(hi >> 56);
            u32 b01 = (u32)(hi >> 48);
            bool p1 = state < (1u << 23);        // need >=1 renorm byte
            bool p2 = state < (1u << 15);        // need exactly 2 (implies p1)
            u32 c1 = (state << 8) | b0;
            u32 c2 = (state << 16) | b01;
            u32 ns = p1 ? c1 : state;
            ns = p2 ? c2 : ns;
            // consume 0/1/2 bytes from reservoir (off critical path)
            u64 h1 = (hi << 8) | (lo >> 56);
            u64 l1 = lo << 8;
            hi = p1 ? h1 : hi;
            lo = p1 ? l1 : lo;
            u64 h2 = (hi << 8) | (lo >> 56);
            u64 l2 = lo << 8;
            hi = p2 ? h2 : hi;
            lo = p2 ? l2 : lo;
            avail -= (int)p1 + (int)p2;
            state = ns;
            acc |= sym << (8 * s);
        }
        g_exp[outw] = acc;
        outw += ((blk & 7) == 7) ? 57u : 1u;

        // branchless refill: append n0's 8 bytes at byte position `avail` when avail<8
        bool need = avail < 8;
        unsigned a = need ? (unsigned)avail : 8u;
        unsigned a4 = a * 4u;          // <= 32, double-shift avoids shift-by-64 UB
        unsigned s4 = (8u - a) * 4u;   // <= 32
        u64 add_hi = (n0 >> a4) >> a4;
        u64 add_lo = (n0 << s4) << s4;
        hi = need ? (hi | add_hi) : hi;
        lo = need ? (lo | add_lo) : lo;
        n0 = need ? n1 : n0;
        n1 = need ? n2 : n1;
        n2 = need ? bswap_pair(fresh) : n2;
        ptr += need ? 1 : 0;
        avail += need ? 8 : 0;
    }
}

// ---------------- gather: out[l, :] = f32(bf16(exp<<8 | man)) of row x[l] ----------------
__global__ void __launch_bounds__(256)
k_gather(const int* __restrict__ x, float4* __restrict__ out) {
    int l = blockIdx.x * 4 + (threadIdx.x >> 6);
    int c = threadIdx.x & 63;
    int row = x[l];
    u32 e = g_exp[row * 64 + c];
    u32 m = g_man[row * 64 + c];
    float4 o;
    o.x = __uint_as_float(((e & 0xFFu) << 24) | ((m & 0xFFu) << 16));
    o.y = __uint_as_float((((e >> 8) & 0xFFu) << 24) | (((m >> 8) & 0xFFu) << 16));
    o.z = __uint_as_float((((e >> 16) & 0xFFu) << 24) | (((m >> 16) & 0xFFu) << 16));
    o.w = __uint_as_float((e & 0xFF000000u) | ((m >> 24) << 16));
    out[(size_t)l * 64 + (size_t)c] = o;
}

// ---------------- launch ----------------
extern "C" void kernel_launch(void* const* d_in, const int* in_sizes, int n_in,
                              void* d_out, int out_size) {
    const int* x       = (const int*)d_in[0];
    const int* stream  = (const int*)d_in[1];
    const int* states  = (const int*)d_in[2];
    const int* tables  = (const int*)d_in[3];
    const int* slotmap = (const int*)d_in[4];
    const int* toffs   = (const int*)d_in[5];
    // d_in[6] = tile_max_lens (uniform; unused)
    const int* manraw  = (const int*)d_in[7];
    float* out = (float*)d_out;

    k_build_lut<<<16, 256>>>(tables, slotmap);

    int n4s = (NT * SLEN) / 4;          // 8,389,632
    k_pack_stream<<<(n4s + 255) / 256, 256>>>((const int4*)stream, n4s);

    int n4m = (NEMB * 256) / 4;         // 4,194,304
    k_pack_man<<<(n4m + 255) / 256, 256>>>((const int4*)manraw, n4m);

    k_decode<<<512, 32>>>(toffs, states);

    k_gather<<<65536, 256>>>(x, (float4*)out);
}